// round 13
// baseline (speedup 1.0000x reference)
#include <cuda_runtime.h>
#include <cstdint>

#define N_NODES   100000
#define N_EDGES   1600000
#define D         128
#define N_GRAPHS  512
#define N_CLASSES 4
#define SCAN_BS   1024
#define SCAN_NBLK ((N_NODES + SCAN_BS - 1) / SCAN_BS)   // 98

// ---------------- scratch (device globals; 16B aligned for wide ops) --------
__device__ __align__(16) float g_agg[N_NODES * D];   // tf32-rounded fp32
__device__ __align__(16) float g_h1 [N_NODES * D];   // tf32-rounded fp32
__device__ __align__(16) float g_h2 [N_NODES * D];   // exact fp32
__device__ __align__(16) float g_z1 [N_NODES * D];   // x @ W1r^T + b1
__device__ __align__(16) float g_xr [N_NODES * D];   // tf32-rounded x
__device__ __align__(16) float g_wr [4 * D * D];     // tf32-rounded weights
__device__ int g_deg   [N_NODES];
__device__ int g_incl  [N_NODES];
__device__ int g_rowptr[N_NODES + 1];
__device__ int g_cursor[N_NODES];
__device__ int g_csr   [N_EDGES];
__device__ int g_bsum  [SCAN_NBLK];
__device__ int g_boff  [SCAN_NBLK];
__device__ int g_is64;

// ---------------- tf32 rounding helper ----------------
__device__ __forceinline__ float round_tf32(float f) {
    uint32_t r;
    asm("cvt.rna.tf32.f32 %0, %1;" : "=r"(r) : "f"(f));
    return __uint_as_float(r);
}

// ---------------- dtype detection ----------------
__global__ void detect_kernel(const void* ei) {
    if (threadIdx.x == 0 && blockIdx.x == 0) {
        const unsigned long long* p = (const unsigned long long*)ei;
        int ok64 = 1;
        for (int i = 0; i < 16; i++)
            if (p[i] >= (unsigned long long)N_NODES) { ok64 = 0; break; }
        g_is64 = ok64;
    }
}

__device__ __forceinline__ int load_idx(const void* base, long long i) {
    return g_is64 ? (int)((const long long*)base)[i]
                  : ((const int*)base)[i];
}

// ---------------- fp32 -> tf32-rounded fp32 convert ----------------
__global__ void convert_tf32_kernel(const float4* __restrict__ in4,
                                    float4* __restrict__ out4, int n4) {
    int i = blockIdx.x * blockDim.x + threadIdx.x;
    int stride = gridDim.x * blockDim.x;
    for (; i < n4; i += stride) {
        float4 v = in4[i];
        v.x = round_tf32(v.x); v.y = round_tf32(v.y);
        v.z = round_tf32(v.z); v.w = round_tf32(v.w);
        out4[i] = v;
    }
}

__global__ void convert_w_kernel(const float* __restrict__ w0, const float* __restrict__ w1,
                                 const float* __restrict__ w2, const float* __restrict__ w3,
                                 float* __restrict__ dst) {
    int i = blockIdx.x * blockDim.x + threadIdx.x;
    if (i >= 4 * D * D) return;
    int m = i >> 14, k = i & (D * D - 1);
    const float* src = (m == 0) ? w0 : (m == 1) ? w1 : (m == 2) ? w2 : w3;
    dst[i] = round_tf32(src[k]);
}

// ---------------- CSR build ----------------
__global__ void zero_int_kernel(int* __restrict__ p, int n) {
    int i = blockIdx.x * blockDim.x + threadIdx.x;
    int stride = gridDim.x * blockDim.x;
    for (; i < n; i += stride) p[i] = 0;
}

__global__ void deg_kernel(const void* __restrict__ ei, int* __restrict__ deg, int ne) {
    int i = blockIdx.x * blockDim.x + threadIdx.x;
    int stride = gridDim.x * blockDim.x;
    for (; i < ne; i += stride) {
        int d = load_idx(ei, (long long)N_EDGES + i);
        if ((unsigned)d < (unsigned)N_NODES)
            atomicAdd(&deg[d], 1);
    }
}

__global__ void scan1_kernel(const int* __restrict__ deg, int* __restrict__ incl,
                             int* __restrict__ bsum, int n) {
    __shared__ int s[SCAN_BS];
    int i = blockIdx.x * SCAN_BS + threadIdx.x;
    int v = (i < n) ? deg[i] : 0;
    s[threadIdx.x] = v;
    __syncthreads();
    for (int off = 1; off < SCAN_BS; off <<= 1) {
        int t = (threadIdx.x >= off) ? s[threadIdx.x - off] : 0;
        __syncthreads();
        s[threadIdx.x] += t;
        __syncthreads();
    }
    if (i < n) incl[i] = s[threadIdx.x];
    if (threadIdx.x == SCAN_BS - 1) bsum[blockIdx.x] = s[SCAN_BS - 1];
}

__global__ void scan2_kernel(const int* __restrict__ bsum, int* __restrict__ boff) {
    if (threadIdx.x == 0) {
        int running = 0;
        for (int b = 0; b < SCAN_NBLK; b++) { boff[b] = running; running += bsum[b]; }
    }
}

__global__ void scan3_kernel(const int* __restrict__ incl, const int* __restrict__ deg,
                             const int* __restrict__ boff, int* __restrict__ rowptr,
                             int* __restrict__ cursor, int n, int total) {
    int i = blockIdx.x * SCAN_BS + threadIdx.x;
    if (i < n) {
        int ex = incl[i] - deg[i] + boff[blockIdx.x];
        rowptr[i] = ex;
        cursor[i] = ex;
        if (i == n - 1) rowptr[n] = total;
    }
}

__global__ void fill_kernel(const void* __restrict__ ei,
                            int* __restrict__ cursor, int* __restrict__ csr, int ne) {
    int i = blockIdx.x * blockDim.x + threadIdx.x;
    int stride = gridDim.x * blockDim.x;
    for (; i < ne; i += stride) {
        int s = load_idx(ei, i);
        int d = load_idx(ei, (long long)N_EDGES + i);
        if ((unsigned)d < (unsigned)N_NODES && (unsigned)s < (unsigned)N_NODES) {
            int pos = atomicAdd(&cursor[d], 1);
            if ((unsigned)pos < (unsigned)N_EDGES) csr[pos] = s;
        }
    }
}

// ---------------- gather (exact R8 structure — do not touch) ----------------
__global__ void gather_kernel(const float4* __restrict__ feat4,
                              const int* __restrict__ rowptr,
                              const int* __restrict__ csr,
                              float4* __restrict__ agg4, int n) {
    int w    = (blockIdx.x * blockDim.x + threadIdx.x) >> 5;
    int lane = threadIdx.x & 31;
    if (w >= n) return;
    int beg = rowptr[w], end = rowptr[w + 1];

    float4 a0 = make_float4(0.f, 0.f, 0.f, 0.f);
    float4 a1 = make_float4(0.f, 0.f, 0.f, 0.f);
    float4 a2 = make_float4(0.f, 0.f, 0.f, 0.f);
    float4 a3 = make_float4(0.f, 0.f, 0.f, 0.f);

    int e = beg;
#pragma unroll 1
    for (; e + 4 <= end; e += 4) {
        int s0 = __ldg(&csr[e]);
        int s1 = __ldg(&csr[e + 1]);
        int s2 = __ldg(&csr[e + 2]);
        int s3 = __ldg(&csr[e + 3]);
        float4 v0 = feat4[(long long)s0 * 32 + lane];
        float4 v1 = feat4[(long long)s1 * 32 + lane];
        float4 v2 = feat4[(long long)s2 * 32 + lane];
        float4 v3 = feat4[(long long)s3 * 32 + lane];
        a0.x += v0.x; a0.y += v0.y; a0.z += v0.z; a0.w += v0.w;
        a1.x += v1.x; a1.y += v1.y; a1.z += v1.z; a1.w += v1.w;
        a2.x += v2.x; a2.y += v2.y; a2.z += v2.z; a2.w += v2.w;
        a3.x += v3.x; a3.y += v3.y; a3.z += v3.z; a3.w += v3.w;
    }
    for (; e < end; e++) {
        int s = __ldg(&csr[e]);
        float4 v = feat4[(long long)s * 32 + lane];
        a0.x += v.x; a0.y += v.y; a0.z += v.z; a0.w += v.w;
    }

    float inv = 1.0f / fmaxf((float)(end - beg), 1.0f);
    float4 acc;
    acc.x = round_tf32((a0.x + a1.x + a2.x + a3.x) * inv);
    acc.y = round_tf32((a0.y + a1.y + a2.y + a3.y) * inv);
    acc.z = round_tf32((a0.z + a1.z + a2.z + a3.z) * inv);
    acc.w = round_tf32((a0.w + a1.w + a2.w + a3.w) * inv);
    agg4[(long long)w * 32 + lane] = acc;
}

// ---------------- tf32 tensor-core GEMM machinery ---------------------------
#define SI3 68   // smem stride words for 64-wide k-half (64 + 4 pad)

__device__ __forceinline__ void mma_tf32(float c[4], const uint32_t a[4], const uint32_t b[2]) {
    asm volatile(
        "mma.sync.aligned.m16n8k8.row.col.f32.tf32.tf32.f32 "
        "{%0,%1,%2,%3}, {%4,%5,%6,%7}, {%8,%9}, {%0,%1,%2,%3};"
        : "+f"(c[0]), "+f"(c[1]), "+f"(c[2]), "+f"(c[3])
        : "r"(a[0]), "r"(a[1]), "r"(a[2]), "r"(a[3]), "r"(b[0]), "r"(b[1]));
}

__device__ __forceinline__ void cp_async16(uint32_t smem_addr, const void* gptr, int sz) {
    asm volatile("cp.async.cg.shared.global [%0], [%1], 16, %2;"
                 :: "r"(smem_addr), "l"(gptr), "r"(sz) : "memory");
}

// fused 2-source GEMM (layer 2): out = relu(agg@Wl^T + xin@Wr^T + b)
__global__ __launch_bounds__(256)
void gemm_fused_kernel(const float* __restrict__ agg,
                       const float* __restrict__ xin,
                       const float* __restrict__ Wl,
                       const float* __restrict__ Wr,
                       const float* __restrict__ bias,
                       float* __restrict__ out,
                       int round_out, int nrows) {
    __shared__ __align__(16) uint32_t sIn[128 * SI3];
    __shared__ __align__(16) uint32_t sW [128 * SI3];

    const int tid   = threadIdx.x;
    const int wid   = tid >> 5;
    const int lane  = tid & 31;
    const int g     = lane >> 2;
    const int t     = lane & 3;
    const int row0  = blockIdx.x * 128;
    const int rbase = (wid >> 1) * 32;
    const int cbase = (wid & 1) * 64;

    const uint32_t sInA = (uint32_t)__cvta_generic_to_shared(sIn);
    const uint32_t sWA  = (uint32_t)__cvta_generic_to_shared(sW);

    float acc[2][8][4];
#pragma unroll
    for (int mi = 0; mi < 2; mi++)
#pragma unroll
        for (int ni = 0; ni < 8; ni++)
#pragma unroll
            for (int j = 0; j < 4; j++) acc[mi][ni][j] = 0.0f;

#pragma unroll 1
    for (int stage = 0; stage < 4; ++stage) {
        const int chunk = stage >> 1;
        const int kh    = (stage & 1) * 64;
        const float* In = chunk ? xin : agg;
        const float* W  = chunk ? Wr  : Wl;

        for (int idx = tid; idx < 128 * 16; idx += 256) {
            int r  = idx >> 4;
            int k4 = (idx & 15) * 4;
            int grow = row0 + r;
            const float* src = (grow < nrows) ? &In[(long long)grow * D + kh + k4] : In;
            int sz = (grow < nrows) ? 16 : 0;
            cp_async16(sInA + (r * SI3 + k4) * 4, src, sz);
        }
        for (int idx = tid; idx < 128 * 16; idx += 256) {
            int c  = idx >> 4;
            int k4 = (idx & 15) * 4;
            cp_async16(sWA + (c * SI3 + k4) * 4, &W[(long long)c * D + kh + k4], 16);
        }
        asm volatile("cp.async.commit_group;" ::: "memory");
        asm volatile("cp.async.wait_group 0;" ::: "memory");
        __syncthreads();

#pragma unroll
        for (int k0 = 0; k0 < 64; k0 += 8) {
            uint32_t a[2][4];
#pragma unroll
            for (int mi = 0; mi < 2; mi++) {
                int r = rbase + mi * 16 + g;
                a[mi][0] = sIn[r * SI3 + k0 + t];
                a[mi][1] = sIn[(r + 8) * SI3 + k0 + t];
                a[mi][2] = sIn[r * SI3 + k0 + t + 4];
                a[mi][3] = sIn[(r + 8) * SI3 + k0 + t + 4];
            }
            uint32_t b[8][2];
#pragma unroll
            for (int ni = 0; ni < 8; ni++) {
                int c = cbase + ni * 8 + g;
                b[ni][0] = sW[c * SI3 + k0 + t];
                b[ni][1] = sW[c * SI3 + k0 + t + 4];
            }
#pragma unroll
            for (int mi = 0; mi < 2; mi++)
#pragma unroll
                for (int ni = 0; ni < 8; ni++)
                    mma_tf32(acc[mi][ni], a[mi], b[ni]);
        }
        __syncthreads();
    }

#pragma unroll
    for (int ni = 0; ni < 8; ni++) {
        int cn = cbase + ni * 8 + 2 * t;
        float bx = __ldg(&bias[cn]);
        float by = __ldg(&bias[cn + 1]);
#pragma unroll
        for (int mi = 0; mi < 2; mi++) {
            int r_lo = row0 + rbase + mi * 16 + g;
            int r_hi = r_lo + 8;
            if (r_lo < nrows) {
                float2 o;
                o.x = fmaxf(acc[mi][ni][0] + bx, 0.f);
                o.y = fmaxf(acc[mi][ni][1] + by, 0.f);
                if (round_out) { o.x = round_tf32(o.x); o.y = round_tf32(o.y); }
                *reinterpret_cast<float2*>(&out[(long long)r_lo * D + cn]) = o;
            }
            if (r_hi < nrows) {
                float2 o;
                o.x = fmaxf(acc[mi][ni][2] + bx, 0.f);
                o.y = fmaxf(acc[mi][ni][3] + by, 0.f);
                if (round_out) { o.x = round_tf32(o.x); o.y = round_tf32(o.y); }
                *reinterpret_cast<float2*>(&out[(long long)r_hi * D + cn]) = o;
            }
        }
    }
}

// single-source GEMM: out = maybe_relu(In@W^T + (Z ? Z[row] : bias)) [opt round]
__global__ __launch_bounds__(256)
void gemm_half_kernel(const float* __restrict__ In,
                      const float* __restrict__ W,
                      const float* __restrict__ bias,
                      const float* __restrict__ Z,    // nullable addend matrix
                      float* __restrict__ out,
                      int do_relu, int round_out, int nrows) {
    __shared__ __align__(16) uint32_t sIn[128 * SI3];
    __shared__ __align__(16) uint32_t sW [128 * SI3];

    const int tid   = threadIdx.x;
    const int wid   = tid >> 5;
    const int lane  = tid & 31;
    const int g     = lane >> 2;
    const int t     = lane & 3;
    const int row0  = blockIdx.x * 128;
    const int rbase = (wid >> 1) * 32;
    const int cbase = (wid & 1) * 64;

    const uint32_t sInA = (uint32_t)__cvta_generic_to_shared(sIn);
    const uint32_t sWA  = (uint32_t)__cvta_generic_to_shared(sW);

    float acc[2][8][4];
#pragma unroll
    for (int mi = 0; mi < 2; mi++)
#pragma unroll
        for (int ni = 0; ni < 8; ni++)
#pragma unroll
            for (int j = 0; j < 4; j++) acc[mi][ni][j] = 0.0f;

#pragma unroll 1
    for (int kh = 0; kh < D; kh += 64) {
        for (int idx = tid; idx < 128 * 16; idx += 256) {
            int r  = idx >> 4;
            int k4 = (idx & 15) * 4;
            int grow = row0 + r;
            const float* src = (grow < nrows) ? &In[(long long)grow * D + kh + k4] : In;
            int sz = (grow < nrows) ? 16 : 0;
            cp_async16(sInA + (r * SI3 + k4) * 4, src, sz);
        }
        for (int idx = tid; idx < 128 * 16; idx += 256) {
            int c  = idx >> 4;
            int k4 = (idx & 15) * 4;
            cp_async16(sWA + (c * SI3 + k4) * 4, &W[(long long)c * D + kh + k4], 16);
        }
        asm volatile("cp.async.commit_group;" ::: "memory");
        asm volatile("cp.async.wait_group 0;" ::: "memory");
        __syncthreads();

#pragma unroll
        for (int k0 = 0; k0 < 64; k0 += 8) {
            uint32_t a[2][4];
#pragma unroll
            for (int mi = 0; mi < 2; mi++) {
                int r = rbase + mi * 16 + g;
                a[mi][0] = sIn[r * SI3 + k0 + t];
                a[mi][1] = sIn[(r + 8) * SI3 + k0 + t];
                a[mi][2] = sIn[r * SI3 + k0 + t + 4];
                a[mi][3] = sIn[(r + 8) * SI3 + k0 + t + 4];
            }
            uint32_t b[8][2];
#pragma unroll
            for (int ni = 0; ni < 8; ni++) {
                int c = cbase + ni * 8 + g;
                b[ni][0] = sW[c * SI3 + k0 + t];
                b[ni][1] = sW[c * SI3 + k0 + t + 4];
            }
#pragma unroll
            for (int mi = 0; mi < 2; mi++)
#pragma unroll
                for (int ni = 0; ni < 8; ni++)
                    mma_tf32(acc[mi][ni], a[mi], b[ni]);
        }
        __syncthreads();
    }

#pragma unroll
    for (int ni = 0; ni < 8; ni++) {
        int cn = cbase + ni * 8 + 2 * t;
        float bx = 0.f, by = 0.f;
        if (!Z) { bx = __ldg(&bias[cn]); by = __ldg(&bias[cn + 1]); }
#pragma unroll
        for (int mi = 0; mi < 2; mi++) {
            int r_lo = row0 + rbase + mi * 16 + g;
            int r_hi = r_lo + 8;
            if (r_lo < nrows) {
                float2 base = Z ? *reinterpret_cast<const float2*>(&Z[(long long)r_lo * D + cn])
                                : make_float2(bx, by);
                float2 o;
                o.x = acc[mi][ni][0] + base.x;
                o.y = acc[mi][ni][1] + base.y;
                if (do_relu)   { o.x = fmaxf(o.x, 0.f);   o.y = fmaxf(o.y, 0.f); }
                if (round_out) { o.x = round_tf32(o.x);   o.y = round_tf32(o.y); }
                *reinterpret_cast<float2*>(&out[(long long)r_lo * D + cn]) = o;
            }
            if (r_hi < nrows) {
                float2 base = Z ? *reinterpret_cast<const float2*>(&Z[(long long)r_hi * D + cn])
                                : make_float2(bx, by);
                float2 o;
                o.x = acc[mi][ni][2] + base.x;
                o.y = acc[mi][ni][3] + base.y;
                if (do_relu)   { o.x = fmaxf(o.x, 0.f);   o.y = fmaxf(o.y, 0.f); }
                if (round_out) { o.x = round_tf32(o.x);   o.y = round_tf32(o.y); }
                *reinterpret_cast<float2*>(&out[(long long)r_hi * D + cn]) = o;
            }
        }
    }
}

// ---------------- fused pool + head (batch is sorted) -----------------------
__device__ __forceinline__ int lower_bound_idx(const void* a, int n, int v) {
    int lo = 0, hi = n;
    while (lo < hi) {
        int mid = (lo + hi) >> 1;
        int av = g_is64 ? (int)((const long long*)a)[mid] : ((const int*)a)[mid];
        if (av < v) lo = mid + 1; else hi = mid;
    }
    return lo;
}

__global__ void pool_head_kernel(const float* __restrict__ h,
                                 const void* __restrict__ batch,
                                 const float* __restrict__ Wlin,
                                 const float* __restrict__ blin,
                                 float* __restrict__ out) {
    __shared__ float sp[D];
    int g = blockIdx.x;
    int t = threadIdx.x;
    int start = lower_bound_idx(batch, N_NODES, g);
    int end   = lower_bound_idx(batch, N_NODES, g + 1);

    float acc = 0.0f;
    for (int i = start; i < end; i++)
        acc += h[(long long)i * D + t];
    float inv = 1.0f / fmaxf((float)(end - start), 1.0f);
    sp[t] = acc * inv;
    __syncthreads();

    int w = t >> 5, lane = t & 31;
    float v = sp[lane]      * Wlin[w * D + lane]
            + sp[lane + 32] * Wlin[w * D + lane + 32]
            + sp[lane + 64] * Wlin[w * D + lane + 64]
            + sp[lane + 96] * Wlin[w * D + lane + 96];
#pragma unroll
    for (int off = 16; off > 0; off >>= 1)
        v += __shfl_down_sync(0xFFFFFFFFu, v, off);
    if (lane == 0) out[g * N_CLASSES + w] = v + blin[w];
}

// ---------------- launch ----------------------------------------------------
extern "C" void kernel_launch(void* const* d_in, const int* in_sizes, int n_in,
                              void* d_out, int out_size) {
    const float *x = 0, *W1l = 0, *b1 = 0, *W1r = 0, *W2l = 0, *b2 = 0,
                *W2r = 0, *Wlin = 0, *blin = 0;
    const void *ei = 0, *batch = 0;
    int nW = 0, nb = 0;
    for (int i = 0; i < n_in; i++) {
        const void* p = d_in[i];
        switch (in_sizes[i]) {
            case N_NODES * D:      x     = (const float*)p; break;
            case 2 * N_EDGES:      ei    = p;               break;
            case N_NODES:          batch = p;               break;
            case D * D:
                if      (nW == 0) W1l = (const float*)p;
                else if (nW == 1) W1r = (const float*)p;
                else if (nW == 2) W2l = (const float*)p;
                else              W2r = (const float*)p;
                nW++; break;
            case D:
                if (nb == 0) b1 = (const float*)p; else b2 = (const float*)p;
                nb++; break;
            case N_CLASSES * D:    Wlin  = (const float*)p;  break;
            case N_CLASSES:        blin  = (const float*)p;  break;
        }
    }
    float* out = (float*)d_out;
    if (!x || !ei || !batch || !W1l || !W1r || !W2l || !W2r || !b1 || !b2 || !Wlin || !blin)
        return;

    float *agg, *h1, *h2, *z1, *xr, *wr;
    int *deg, *incl, *rowptr, *cursor, *csr, *bsum, *boff;
    cudaGetSymbolAddress((void**)&agg,    g_agg);
    cudaGetSymbolAddress((void**)&h1,     g_h1);
    cudaGetSymbolAddress((void**)&h2,     g_h2);
    cudaGetSymbolAddress((void**)&z1,     g_z1);
    cudaGetSymbolAddress((void**)&xr,     g_xr);
    cudaGetSymbolAddress((void**)&wr,     g_wr);
    cudaGetSymbolAddress((void**)&deg,    g_deg);
    cudaGetSymbolAddress((void**)&incl,   g_incl);
    cudaGetSymbolAddress((void**)&rowptr, g_rowptr);
    cudaGetSymbolAddress((void**)&cursor, g_cursor);
    cudaGetSymbolAddress((void**)&csr,    g_csr);
    cudaGetSymbolAddress((void**)&bsum,   g_bsum);
    cudaGetSymbolAddress((void**)&boff,   g_boff);

    // side stream + fork/join events (created once on the uncaptured
    // correctness call; reused identically during graph capture)
    static cudaStream_t s1 = 0;
    static cudaEvent_t  e0 = 0, e1 = 0;
    if (!s1) {
        cudaStreamCreateWithFlags(&s1, cudaStreamNonBlocking);
        cudaEventCreateWithFlags(&e0, cudaEventDisableTiming);
        cudaEventCreateWithFlags(&e1, cudaEventDisableTiming);
    }

    const int gath_blocks = (N_NODES * 32 + 255) / 256;
    const int gemm_blocks = (N_NODES + 127) / 128;

    // ---- fork: branch A (converts + z1) runs concurrently with CSR+gather1 --
    cudaEventRecord(e0, 0);
    cudaStreamWaitEvent(s1, e0, 0);
    convert_tf32_kernel<<<1024, 256, 0, s1>>>((const float4*)x, (float4*)xr, N_NODES * D / 4);
    convert_w_kernel<<<(4 * D * D + 255) / 256, 256, 0, s1>>>(W1l, W1r, W2l, W2r, wr);
    // z1 = xr @ W1r^T + b1   (no relu, no round)
    gemm_half_kernel<<<gemm_blocks, 256, 0, s1>>>(xr, wr + 1 * D * D, b1, (const float*)0,
                                                  z1, 0, 0, N_NODES);
    cudaEventRecord(e1, s1);

    // ---- main path: CSR build + gather1 ----
    detect_kernel<<<1, 32>>>(ei);
    zero_int_kernel<<<256, 256>>>(deg, N_NODES);
    deg_kernel<<<1024, 256>>>(ei, deg, N_EDGES);
    scan1_kernel<<<SCAN_NBLK, SCAN_BS>>>(deg, incl, bsum, N_NODES);
    scan2_kernel<<<1, 32>>>(bsum, boff);
    scan3_kernel<<<SCAN_NBLK, SCAN_BS>>>(incl, deg, boff, rowptr, cursor, N_NODES, N_EDGES);
    fill_kernel<<<1024, 256>>>(ei, cursor, csr, N_EDGES);
    gather_kernel<<<gath_blocks, 256>>>((const float4*)x, rowptr, csr, (float4*)agg, N_NODES);

    // ---- join, then h1 = relu(agg @ W1l^T + z1), tf32-rounded ----
    cudaStreamWaitEvent(0, e1, 0);
    gemm_half_kernel<<<gemm_blocks, 256>>>(agg, wr + 0 * D * D, b1, z1, h1, 1, 1, N_NODES);

    // ---- layer 2 (fused) ----
    gather_kernel<<<gath_blocks, 256>>>((const float4*)h1, rowptr, csr, (float4*)agg, N_NODES);
    gemm_fused_kernel<<<gemm_blocks, 256>>>(agg, h1, wr + 2 * D * D, wr + 3 * D * D, b2,
                                            h2, 0, N_NODES);

    // ---- pool + head ----
    pool_head_kernel<<<N_GRAPHS, 128>>>(h2, batch, Wlin, blin, out);
}

// round 14
// speedup vs baseline: 1.0913x; 1.0913x over previous
#include <cuda_runtime.h>
#include <cstdint>

#define N_NODES   100000
#define N_EDGES   1600000
#define D         128
#define N_GRAPHS  512
#define N_CLASSES 4
#define SCAN_BS   1024
#define SCAN_NBLK ((N_NODES + SCAN_BS - 1) / SCAN_BS)   // 98

// ---------------- scratch (device globals; 16B aligned for wide ops) --------
__device__ __align__(16) float g_agg[N_NODES * D];   // tf32-rounded fp32
__device__ __align__(16) float g_h1 [N_NODES * D];   // tf32-rounded fp32
__device__ __align__(16) float g_h2 [N_NODES * D];   // exact fp32
__device__ __align__(16) float g_xr [N_NODES * D];   // tf32-rounded x
__device__ __align__(16) float g_wr [4 * D * D];     // tf32-rounded weights
__device__ int g_deg   [N_NODES];
__device__ int g_incl  [N_NODES];
__device__ int g_rowptr[N_NODES + 1];
__device__ int g_cursor[N_NODES];
__device__ int g_csr   [N_EDGES];
__device__ int g_bsum  [SCAN_NBLK];
__device__ int g_is64;   // published by deg_kernel block 0 (for pool kernel)

// ---------------- tf32 rounding helper ----------------
__device__ __forceinline__ float round_tf32(float f) {
    uint32_t r;
    asm("cvt.rna.tf32.f32 %0, %1;" : "=r"(r) : "f"(f));
    return __uint_as_float(r);
}

// ---------------- per-warp dtype detection (no kernel launch) ---------------
// int64 edge data: every u64 word is a node id < N_NODES. int32: packed pairs
// of random node ids are >= 2^32 with overwhelming probability.
__device__ __forceinline__ bool detect_is64(const void* ei) {
    const unsigned long long* p = (const unsigned long long*)ei;
    int lane = threadIdx.x & 31;
    unsigned long long v = __ldg(&p[lane & 15]);
    return __all_sync(0xFFFFFFFFu, v < (unsigned long long)N_NODES);
}

// ---------------- prep: convert x->xr, weights->wr, zero deg  (one launch) --
// blocks [0,1024): x convert; [1024,1088): weights; [1088,1152): zero deg
__global__ void prep_kernel(const float4* __restrict__ x4,
                            float4* __restrict__ xr4,
                            const float* __restrict__ w0, const float* __restrict__ w1,
                            const float* __restrict__ w2, const float* __restrict__ w3,
                            float* __restrict__ wr,
                            int* __restrict__ deg) {
    int b = blockIdx.x;
    if (b < 1024) {
        int n4 = N_NODES * D / 4;
        int i = b * 256 + threadIdx.x;
        int stride = 1024 * 256;
        for (; i < n4; i += stride) {
            float4 v = x4[i];
            v.x = round_tf32(v.x); v.y = round_tf32(v.y);
            v.z = round_tf32(v.z); v.w = round_tf32(v.w);
            xr4[i] = v;
        }
    } else if (b < 1088) {
        int i = (b - 1024) * 256 + threadIdx.x;   // 0 .. 16383 (float4 units)
        if (i < 4 * D * D / 4) {
            int m  = i >> 12;                      // 4096 float4 per matrix
            int k4 = (i & 4095) * 4;
            const float* src = (m == 0) ? w0 : (m == 1) ? w1 : (m == 2) ? w2 : w3;
            float4 v = *reinterpret_cast<const float4*>(&src[k4]);
            v.x = round_tf32(v.x); v.y = round_tf32(v.y);
            v.z = round_tf32(v.z); v.w = round_tf32(v.w);
            *reinterpret_cast<float4*>(&wr[m * D * D + k4]) = v;
        }
    } else {
        int i = (b - 1088) * 256 + threadIdx.x;
        int stride = 64 * 256;
        for (; i < N_NODES; i += stride) deg[i] = 0;
    }
}

// ---------------- CSR build ----------------
__global__ void deg_kernel(const void* __restrict__ ei, int* __restrict__ deg, int ne) {
    bool is64 = detect_is64(ei);
    if (blockIdx.x == 0 && threadIdx.x == 0) g_is64 = is64 ? 1 : 0;
    int i = blockIdx.x * blockDim.x + threadIdx.x;
    int stride = gridDim.x * blockDim.x;
    for (; i < ne; i += stride) {
        int d = is64 ? (int)((const long long*)ei)[(long long)N_EDGES + i]
                     : ((const int*)ei)[(long long)N_EDGES + i];
        if ((unsigned)d < (unsigned)N_NODES)
            atomicAdd(&deg[d], 1);
    }
}

__global__ void scan1_kernel(const int* __restrict__ deg, int* __restrict__ incl,
                             int* __restrict__ bsum, int n) {
    __shared__ int s[SCAN_BS];
    int i = blockIdx.x * SCAN_BS + threadIdx.x;
    int v = (i < n) ? deg[i] : 0;
    s[threadIdx.x] = v;
    __syncthreads();
    for (int off = 1; off < SCAN_BS; off <<= 1) {
        int t = (threadIdx.x >= off) ? s[threadIdx.x - off] : 0;
        __syncthreads();
        s[threadIdx.x] += t;
        __syncthreads();
    }
    if (i < n) incl[i] = s[threadIdx.x];
    if (threadIdx.x == SCAN_BS - 1) bsum[blockIdx.x] = s[SCAN_BS - 1];
}

// scan2 merged in: each block derives its own offset from bsum[0..blockIdx)
__global__ void scan3_kernel(const int* __restrict__ incl, const int* __restrict__ deg,
                             const int* __restrict__ bsum, int* __restrict__ rowptr,
                             int* __restrict__ cursor, int n, int total) {
    __shared__ int s_off;
    if (threadIdx.x == 0) s_off = 0;
    __syncthreads();
    if (threadIdx.x < blockIdx.x)          // blockIdx.x <= 97 < SCAN_BS
        atomicAdd(&s_off, bsum[threadIdx.x]);
    __syncthreads();
    int i = blockIdx.x * SCAN_BS + threadIdx.x;
    if (i < n) {
        int ex = incl[i] - deg[i] + s_off;
        rowptr[i] = ex;
        cursor[i] = ex;
        if (i == n - 1) rowptr[n] = total;
    }
}

__global__ void fill_kernel(const void* __restrict__ ei,
                            int* __restrict__ cursor, int* __restrict__ csr, int ne) {
    bool is64 = detect_is64(ei);
    int i = blockIdx.x * blockDim.x + threadIdx.x;
    int stride = gridDim.x * blockDim.x;
    for (; i < ne; i += stride) {
        int s = is64 ? (int)((const long long*)ei)[i] : ((const int*)ei)[i];
        int d = is64 ? (int)((const long long*)ei)[(long long)N_EDGES + i]
                     : ((const int*)ei)[(long long)N_EDGES + i];
        if ((unsigned)d < (unsigned)N_NODES && (unsigned)s < (unsigned)N_NODES) {
            int pos = atomicAdd(&cursor[d], 1);
            if ((unsigned)pos < (unsigned)N_EDGES) csr[pos] = s;
        }
    }
}

// ---------------- gather (exact R8 structure — frozen) ----------------------
__global__ void gather_kernel(const float4* __restrict__ feat4,
                              const int* __restrict__ rowptr,
                              const int* __restrict__ csr,
                              float4* __restrict__ agg4, int n) {
    int w    = (blockIdx.x * blockDim.x + threadIdx.x) >> 5;
    int lane = threadIdx.x & 31;
    if (w >= n) return;
    int beg = rowptr[w], end = rowptr[w + 1];

    float4 a0 = make_float4(0.f, 0.f, 0.f, 0.f);
    float4 a1 = make_float4(0.f, 0.f, 0.f, 0.f);
    float4 a2 = make_float4(0.f, 0.f, 0.f, 0.f);
    float4 a3 = make_float4(0.f, 0.f, 0.f, 0.f);

    int e = beg;
#pragma unroll 1
    for (; e + 4 <= end; e += 4) {
        int s0 = __ldg(&csr[e]);
        int s1 = __ldg(&csr[e + 1]);
        int s2 = __ldg(&csr[e + 2]);
        int s3 = __ldg(&csr[e + 3]);
        float4 v0 = feat4[(long long)s0 * 32 + lane];
        float4 v1 = feat4[(long long)s1 * 32 + lane];
        float4 v2 = feat4[(long long)s2 * 32 + lane];
        float4 v3 = feat4[(long long)s3 * 32 + lane];
        a0.x += v0.x; a0.y += v0.y; a0.z += v0.z; a0.w += v0.w;
        a1.x += v1.x; a1.y += v1.y; a1.z += v1.z; a1.w += v1.w;
        a2.x += v2.x; a2.y += v2.y; a2.z += v2.z; a2.w += v2.w;
        a3.x += v3.x; a3.y += v3.y; a3.z += v3.z; a3.w += v3.w;
    }
    for (; e < end; e++) {
        int s = __ldg(&csr[e]);
        float4 v = feat4[(long long)s * 32 + lane];
        a0.x += v.x; a0.y += v.y; a0.z += v.z; a0.w += v.w;
    }

    float inv = 1.0f / fmaxf((float)(end - beg), 1.0f);
    float4 acc;
    acc.x = round_tf32((a0.x + a1.x + a2.x + a3.x) * inv);
    acc.y = round_tf32((a0.y + a1.y + a2.y + a3.y) * inv);
    acc.z = round_tf32((a0.z + a1.z + a2.z + a3.z) * inv);
    acc.w = round_tf32((a0.w + a1.w + a2.w + a3.w) * inv);
    agg4[(long long)w * 32 + lane] = acc;
}

// ---------------- tf32 tensor-core fused SAGE layer GEMM (frozen) -----------
#define SI3 68   // smem stride words for 64-wide k-half (64 + 4 pad)

__device__ __forceinline__ void mma_tf32(float c[4], const uint32_t a[4], const uint32_t b[2]) {
    asm volatile(
        "mma.sync.aligned.m16n8k8.row.col.f32.tf32.tf32.f32 "
        "{%0,%1,%2,%3}, {%4,%5,%6,%7}, {%8,%9}, {%0,%1,%2,%3};"
        : "+f"(c[0]), "+f"(c[1]), "+f"(c[2]), "+f"(c[3])
        : "r"(a[0]), "r"(a[1]), "r"(a[2]), "r"(a[3]), "r"(b[0]), "r"(b[1]));
}

__device__ __forceinline__ void cp_async16(uint32_t smem_addr, const void* gptr, int sz) {
    asm volatile("cp.async.cg.shared.global [%0], [%1], 16, %2;"
                 :: "r"(smem_addr), "l"(gptr), "r"(sz) : "memory");
}

__global__ __launch_bounds__(256)
void gemm_fused_kernel(const float* __restrict__ agg,
                       const float* __restrict__ xin,
                       const float* __restrict__ Wl,
                       const float* __restrict__ Wr,
                       const float* __restrict__ bias,
                       float* __restrict__ out,
                       int round_out, int nrows) {
    __shared__ __align__(16) uint32_t sIn[128 * SI3];
    __shared__ __align__(16) uint32_t sW [128 * SI3];

    const int tid   = threadIdx.x;
    const int wid   = tid >> 5;
    const int lane  = tid & 31;
    const int g     = lane >> 2;
    const int t     = lane & 3;
    const int row0  = blockIdx.x * 128;
    const int rbase = (wid >> 1) * 32;
    const int cbase = (wid & 1) * 64;

    const uint32_t sInA = (uint32_t)__cvta_generic_to_shared(sIn);
    const uint32_t sWA  = (uint32_t)__cvta_generic_to_shared(sW);

    float acc[2][8][4];
#pragma unroll
    for (int mi = 0; mi < 2; mi++)
#pragma unroll
        for (int ni = 0; ni < 8; ni++)
#pragma unroll
            for (int j = 0; j < 4; j++) acc[mi][ni][j] = 0.0f;

#pragma unroll 1
    for (int stage = 0; stage < 4; ++stage) {
        const int chunk = stage >> 1;
        const int kh    = (stage & 1) * 64;
        const float* In = chunk ? xin : agg;
        const float* W  = chunk ? Wr  : Wl;

        for (int idx = tid; idx < 128 * 16; idx += 256) {
            int r  = idx >> 4;
            int k4 = (idx & 15) * 4;
            int grow = row0 + r;
            const float* src = (grow < nrows) ? &In[(long long)grow * D + kh + k4] : In;
            int sz = (grow < nrows) ? 16 : 0;
            cp_async16(sInA + (r * SI3 + k4) * 4, src, sz);
        }
        for (int idx = tid; idx < 128 * 16; idx += 256) {
            int c  = idx >> 4;
            int k4 = (idx & 15) * 4;
            cp_async16(sWA + (c * SI3 + k4) * 4, &W[(long long)c * D + kh + k4], 16);
        }
        asm volatile("cp.async.commit_group;" ::: "memory");
        asm volatile("cp.async.wait_group 0;" ::: "memory");
        __syncthreads();

#pragma unroll
        for (int k0 = 0; k0 < 64; k0 += 8) {
            uint32_t a[2][4];
#pragma unroll
            for (int mi = 0; mi < 2; mi++) {
                int r = rbase + mi * 16 + g;
                a[mi][0] = sIn[r * SI3 + k0 + t];
                a[mi][1] = sIn[(r + 8) * SI3 + k0 + t];
                a[mi][2] = sIn[r * SI3 + k0 + t + 4];
                a[mi][3] = sIn[(r + 8) * SI3 + k0 + t + 4];
            }
            uint32_t b[8][2];
#pragma unroll
            for (int ni = 0; ni < 8; ni++) {
                int c = cbase + ni * 8 + g;
                b[ni][0] = sW[c * SI3 + k0 + t];
                b[ni][1] = sW[c * SI3 + k0 + t + 4];
            }
#pragma unroll
            for (int mi = 0; mi < 2; mi++)
#pragma unroll
                for (int ni = 0; ni < 8; ni++)
                    mma_tf32(acc[mi][ni], a[mi], b[ni]);
        }
        __syncthreads();
    }

#pragma unroll
    for (int ni = 0; ni < 8; ni++) {
        int cn = cbase + ni * 8 + 2 * t;
        float bx = __ldg(&bias[cn]);
        float by = __ldg(&bias[cn + 1]);
#pragma unroll
        for (int mi = 0; mi < 2; mi++) {
            int r_lo = row0 + rbase + mi * 16 + g;
            int r_hi = r_lo + 8;
            if (r_lo < nrows) {
                float2 o;
                o.x = fmaxf(acc[mi][ni][0] + bx, 0.f);
                o.y = fmaxf(acc[mi][ni][1] + by, 0.f);
                if (round_out) { o.x = round_tf32(o.x); o.y = round_tf32(o.y); }
                *reinterpret_cast<float2*>(&out[(long long)r_lo * D + cn]) = o;
            }
            if (r_hi < nrows) {
                float2 o;
                o.x = fmaxf(acc[mi][ni][2] + bx, 0.f);
                o.y = fmaxf(acc[mi][ni][3] + by, 0.f);
                if (round_out) { o.x = round_tf32(o.x); o.y = round_tf32(o.y); }
                *reinterpret_cast<float2*>(&out[(long long)r_hi * D + cn]) = o;
            }
        }
    }
}

// ---------------- fused pool + head (batch is sorted) -----------------------
__device__ __forceinline__ int lower_bound_idx(const void* a, int n, int v) {
    int lo = 0, hi = n;
    while (lo < hi) {
        int mid = (lo + hi) >> 1;
        int av = g_is64 ? (int)((const long long*)a)[mid] : ((const int*)a)[mid];
        if (av < v) lo = mid + 1; else hi = mid;
    }
    return lo;
}

__global__ void pool_head_kernel(const float* __restrict__ h,
                                 const void* __restrict__ batch,
                                 const float* __restrict__ Wlin,
                                 const float* __restrict__ blin,
                                 float* __restrict__ out) {
    __shared__ float sp[D];
    int g = blockIdx.x;
    int t = threadIdx.x;
    int start = lower_bound_idx(batch, N_NODES, g);
    int end   = lower_bound_idx(batch, N_NODES, g + 1);

    float acc = 0.0f;
    for (int i = start; i < end; i++)
        acc += h[(long long)i * D + t];
    float inv = 1.0f / fmaxf((float)(end - start), 1.0f);
    sp[t] = acc * inv;
    __syncthreads();

    int w = t >> 5, lane = t & 31;
    float v = sp[lane]      * Wlin[w * D + lane]
            + sp[lane + 32] * Wlin[w * D + lane + 32]
            + sp[lane + 64] * Wlin[w * D + lane + 64]
            + sp[lane + 96] * Wlin[w * D + lane + 96];
#pragma unroll
    for (int off = 16; off > 0; off >>= 1)
        v += __shfl_down_sync(0xFFFFFFFFu, v, off);
    if (lane == 0) out[g * N_CLASSES + w] = v + blin[w];
}

// ---------------- launch ----------------------------------------------------
extern "C" void kernel_launch(void* const* d_in, const int* in_sizes, int n_in,
                              void* d_out, int out_size) {
    const float *x = 0, *W1l = 0, *b1 = 0, *W1r = 0, *W2l = 0, *b2 = 0,
                *W2r = 0, *Wlin = 0, *blin = 0;
    const void *ei = 0, *batch = 0;
    int nW = 0, nb = 0;
    for (int i = 0; i < n_in; i++) {
        const void* p = d_in[i];
        switch (in_sizes[i]) {
            case N_NODES * D:      x     = (const float*)p; break;
            case 2 * N_EDGES:      ei    = p;               break;
            case N_NODES:          batch = p;               break;
            case D * D:
                if      (nW == 0) W1l = (const float*)p;
                else if (nW == 1) W1r = (const float*)p;
                else if (nW == 2) W2l = (const float*)p;
                else              W2r = (const float*)p;
                nW++; break;
            case D:
                if (nb == 0) b1 = (const float*)p; else b2 = (const float*)p;
                nb++; break;
            case N_CLASSES * D:    Wlin  = (const float*)p;  break;
            case N_CLASSES:        blin  = (const float*)p;  break;
        }
    }
    float* out = (float*)d_out;
    if (!x || !ei || !batch || !W1l || !W1r || !W2l || !W2r || !b1 || !b2 || !Wlin || !blin)
        return;

    float *agg, *h1, *h2, *xr, *wr;
    int *deg, *incl, *rowptr, *cursor, *csr, *bsum;
    cudaGetSymbolAddress((void**)&agg,    g_agg);
    cudaGetSymbolAddress((void**)&h1,     g_h1);
    cudaGetSymbolAddress((void**)&h2,     g_h2);
    cudaGetSymbolAddress((void**)&xr,     g_xr);
    cudaGetSymbolAddress((void**)&wr,     g_wr);
    cudaGetSymbolAddress((void**)&deg,    g_deg);
    cudaGetSymbolAddress((void**)&incl,   g_incl);
    cudaGetSymbolAddress((void**)&rowptr, g_rowptr);
    cudaGetSymbolAddress((void**)&cursor, g_cursor);
    cudaGetSymbolAddress((void**)&csr,    g_csr);
    cudaGetSymbolAddress((void**)&bsum,   g_bsum);

    const int gath_blocks = (N_NODES * 32 + 255) / 256;
    const int gemm_blocks = (N_NODES + 127) / 128;

    // ---- prep (convert x + convert w + zero deg, one launch) ----
    prep_kernel<<<1152, 256>>>((const float4*)x, (float4*)xr,
                               W1l, W1r, W2l, W2r, wr, deg);

    // ---- CSR build (deg also publishes g_is64) ----
    deg_kernel<<<1024, 256>>>(ei, deg, N_EDGES);
    scan1_kernel<<<SCAN_NBLK, SCAN_BS>>>(deg, incl, bsum, N_NODES);
    scan3_kernel<<<SCAN_NBLK, SCAN_BS>>>(incl, deg, bsum, rowptr, cursor, N_NODES, N_EDGES);
    fill_kernel<<<1024, 256>>>(ei, cursor, csr, N_EDGES);

    // ---- layer 1 ----
    gather_kernel<<<gath_blocks, 256>>>((const float4*)x, rowptr, csr, (float4*)agg, N_NODES);
    gemm_fused_kernel<<<gemm_blocks, 256>>>(agg, xr, wr + 0 * D * D, wr + 1 * D * D, b1,
                                            h1, 1, N_NODES);

    // ---- layer 2 ----
    gather_kernel<<<gath_blocks, 256>>>((const float4*)h1, rowptr, csr, (float4*)agg, N_NODES);
    gemm_fused_kernel<<<gemm_blocks, 256>>>(agg, h1, wr + 2 * D * D, wr + 3 * D * D, b2,
                                            h2, 0, N_NODES);

    // ---- pool + head ----
    pool_head_kernel<<<N_GRAPHS, 128>>>(h2, batch, Wlin, blin, out);
}